// round 3
// baseline (speedup 1.0000x reference)
#include <cuda_runtime.h>
#include <math.h>

#define D 128
#define MAXN 50000
#define MAXE 800000
#define GEMM_ROWS 32

__device__ int  g_cnt[MAXN];
__device__ int  g_offs[MAXN];     // after scatter: end offset per row
__device__ int  g_bsums[64];
__device__ int2 g_edge[MAXE];     // (col, val bits), binned by dest row

// fma.rn.f32x2: packed dual fp32 FMA (sm_100+)
#define FMA2(acc, a, b) \
    asm("fma.rn.f32x2 %0, %1, %2, %0;" : "+l"(acc) : "l"(a), "l"(b))

__device__ __forceinline__ unsigned long long pack_dup(float f) {
    unsigned long long r;
    asm("mov.b64 %0, {%1, %1};" : "=l"(r) : "f"(f));
    return r;
}
__device__ __forceinline__ float lo_f(unsigned long long v) {
    return __uint_as_float((unsigned)(v & 0xffffffffull));
}
__device__ __forceinline__ float hi_f(unsigned long long v) {
    return __uint_as_float((unsigned)(v >> 32));
}

// ---------------- CSR build ----------------

__global__ void zero_cnt_kernel(int n) {
    int i = blockIdx.x * blockDim.x + threadIdx.x;
    if (i < n) g_cnt[i] = 0;
}

__global__ void hist_kernel(const int* __restrict__ row, int E) {
    int e = blockIdx.x * blockDim.x + threadIdx.x;
    if (e < E) atomicAdd(&g_cnt[row[e]], 1);
}

__global__ void scan1_kernel(int n) {
    __shared__ int s[1024];
    int i = blockIdx.x * 1024 + threadIdx.x;
    int v = (i < n) ? g_cnt[i] : 0;
    s[threadIdx.x] = v;
    __syncthreads();
    for (int d = 1; d < 1024; d <<= 1) {
        int t = (threadIdx.x >= d) ? s[threadIdx.x - d] : 0;
        __syncthreads();
        s[threadIdx.x] += t;
        __syncthreads();
    }
    if (i < n) g_offs[i] = s[threadIdx.x] - v;  // exclusive within block
    if (threadIdx.x == 1023) g_bsums[blockIdx.x] = s[1023];
}

// parallel exclusive scan over up to 64 block sums
__global__ void scan2_kernel(int nb) {
    __shared__ int s[64];
    int i = threadIdx.x;
    int v = (i < nb) ? g_bsums[i] : 0;
    s[i] = v;
    __syncthreads();
    for (int d = 1; d < 64; d <<= 1) {
        int t = (i >= d) ? s[i - d] : 0;
        __syncthreads();
        s[i] += t;
        __syncthreads();
    }
    if (i < nb) g_bsums[i] = s[i] - v;  // exclusive
}

__global__ void scan3_kernel(int n) {
    int i = blockIdx.x * blockDim.x + threadIdx.x;
    if (i < n) g_offs[i] += g_bsums[i >> 10];
}

__global__ void scatter_kernel(const int* __restrict__ row, const int* __restrict__ col,
                               const float* __restrict__ vals, int E) {
    int e = blockIdx.x * blockDim.x + threadIdx.x;
    if (e < E) {
        int pos = atomicAdd(&g_offs[row[e]], 1);   // offs becomes END after this kernel
        g_edge[pos] = make_int2(col[e], __float_as_int(vals[e]));
    }
}

// ---------------- fused gather-SpMM + GEMM ----------------
// Block: 128 threads (4 warps), 32 rows.
// Phase 1: each warp gathers 8 rows: s = (1-alpha)*sum(v*input[c]) + alpha*h0,
//          written to smem as duplicated f32x2 pairs.
// Phase 2: register-blocked FMA2 GEMM: out = theta*(S@W) + (1-theta)*S.

__global__ void __launch_bounds__(128) fused_kernel(
        const float* __restrict__ input,
        const float* __restrict__ h0,
        const float* __restrict__ W,
        const float* __restrict__ lamda_p,
        const float* __restrict__ alpha_p,
        const int* __restrict__ l_p,
        float* __restrict__ out, int N) {
    __shared__ unsigned long long sp[GEMM_ROWS][D];  // 32 KB, sp[r][k] = (s,s)
    int tid  = threadIdx.x;
    int lane = tid & 31;
    int w    = tid >> 5;
    int rowBase = blockIdx.x * GEMM_ROWS;

    float a = *alpha_p, oma = 1.f - a;
    const float4* in4 = (const float4*)input;

    // ---- phase 1: gather 8 rows per warp ----
#pragma unroll 1
    for (int i = 0; i < 8; i++) {
        int rr = w * 8 + i;
        int gr = rowBase + rr;
        float ax = 0.f, ay = 0.f, az = 0.f, aw = 0.f;
        if (gr < N) {
            int end = g_offs[gr];
            int beg = end - g_cnt[gr];
            int j = beg;
            for (; j + 4 <= end; j += 4) {
                int2 e0 = g_edge[j],   e1 = g_edge[j+1];
                int2 e2 = g_edge[j+2], e3 = g_edge[j+3];
                float4 x0 = in4[(size_t)e0.x * 32 + lane];
                float4 x1 = in4[(size_t)e1.x * 32 + lane];
                float4 x2 = in4[(size_t)e2.x * 32 + lane];
                float4 x3 = in4[(size_t)e3.x * 32 + lane];
                float v0 = __int_as_float(e0.y), v1 = __int_as_float(e1.y);
                float v2 = __int_as_float(e2.y), v3 = __int_as_float(e3.y);
                ax = fmaf(v0, x0.x, fmaf(v1, x1.x, fmaf(v2, x2.x, fmaf(v3, x3.x, ax))));
                ay = fmaf(v0, x0.y, fmaf(v1, x1.y, fmaf(v2, x2.y, fmaf(v3, x3.y, ay))));
                az = fmaf(v0, x0.z, fmaf(v1, x1.z, fmaf(v2, x2.z, fmaf(v3, x3.z, az))));
                aw = fmaf(v0, x0.w, fmaf(v1, x1.w, fmaf(v2, x2.w, fmaf(v3, x3.w, aw))));
            }
            for (; j < end; j++) {
                int2 e = g_edge[j];
                float v = __int_as_float(e.y);
                float4 x = in4[(size_t)e.x * 32 + lane];
                ax = fmaf(v, x.x, ax);
                ay = fmaf(v, x.y, ay);
                az = fmaf(v, x.z, az);
                aw = fmaf(v, x.w, aw);
            }
            float4 h = ((const float4*)h0)[(size_t)gr * 32 + lane];
            ax = fmaf(oma, ax, a * h.x);
            ay = fmaf(oma, ay, a * h.y);
            az = fmaf(oma, az, a * h.z);
            aw = fmaf(oma, aw, a * h.w);
        }
        sp[rr][lane * 4 + 0] = pack_dup(ax);
        sp[rr][lane * 4 + 1] = pack_dup(ay);
        sp[rr][lane * 4 + 2] = pack_dup(az);
        sp[rr][lane * 4 + 3] = pack_dup(aw);
    }
    __syncthreads();

    // ---- phase 2: GEMM, 8 rows per warp ----
    unsigned long long acc01[8], acc23[8];
#pragma unroll
    for (int r = 0; r < 8; r++) { acc01[r] = 0ull; acc23[r] = 0ull; }

    const ulonglong2* W2 = (const ulonglong2*)W;

#pragma unroll 4
    for (int kg = 0; kg < 32; kg++) {
        int k0 = kg * 4;
        ulonglong2 w0 = __ldg(&W2[(size_t)(k0 + 0) * 32 + lane]);
        ulonglong2 w1 = __ldg(&W2[(size_t)(k0 + 1) * 32 + lane]);
        ulonglong2 w2 = __ldg(&W2[(size_t)(k0 + 2) * 32 + lane]);
        ulonglong2 w3 = __ldg(&W2[(size_t)(k0 + 3) * 32 + lane]);
#pragma unroll
        for (int r = 0; r < 8; r++) {
            int rr = w * 8 + r;
            const ulonglong2* srow = (const ulonglong2*)sp[rr];
            ulonglong2 sA = srow[kg * 2 + 0];
            ulonglong2 sB = srow[kg * 2 + 1];
            FMA2(acc01[r], w0.x, sA.x); FMA2(acc23[r], w0.y, sA.x);
            FMA2(acc01[r], w1.x, sA.y); FMA2(acc23[r], w1.y, sA.y);
            FMA2(acc01[r], w2.x, sB.x); FMA2(acc23[r], w2.y, sB.x);
            FMA2(acc01[r], w3.x, sB.y); FMA2(acc23[r], w3.y, sB.y);
        }
    }

    float theta = logf(*lamda_p / (float)(*l_p) + 1.0f);
    float om = 1.0f - theta;

#pragma unroll
    for (int r = 0; r < 8; r++) {
        int rr = w * 8 + r;
        int gr = rowBase + rr;
        if (gr >= N) continue;
        const ulonglong2* srow = (const ulonglong2*)sp[rr];
        ulonglong2 s01 = srow[lane * 2 + 0];
        ulonglong2 s23 = srow[lane * 2 + 1];
        float4 o;
        o.x = fmaf(theta, lo_f(acc01[r]), om * lo_f(s01.x));
        o.y = fmaf(theta, hi_f(acc01[r]), om * lo_f(s01.y));
        o.z = fmaf(theta, lo_f(acc23[r]), om * lo_f(s23.x));
        o.w = fmaf(theta, hi_f(acc23[r]), om * lo_f(s23.y));
        ((float4*)out)[(size_t)gr * 32 + lane] = o;
    }
}

// ---------------- launch ----------------

extern "C" void kernel_launch(void* const* d_in, const int* in_sizes, int n_in,
                              void* d_out, int out_size) {
    const float* input  = (const float*)d_in[0];
    const float* h0     = (const float*)d_in[1];
    const float* vals   = (const float*)d_in[2];
    const float* W      = (const float*)d_in[3];
    const float* lamda  = (const float*)d_in[4];
    const float* alpha  = (const float*)d_in[5];
    const int*   row    = (const int*)d_in[6];
    const int*   col    = (const int*)d_in[7];
    const int*   l      = (const int*)d_in[8];
    float* out = (float*)d_out;

    int N = in_sizes[0] / D;
    int E = in_sizes[2];

    zero_cnt_kernel<<<(N + 255) / 256, 256>>>(N);
    hist_kernel<<<(E + 255) / 256, 256>>>(row, E);
    int nScanBlocks = (N + 1023) / 1024;
    scan1_kernel<<<nScanBlocks, 1024>>>(N);
    scan2_kernel<<<1, 64>>>(nScanBlocks);
    scan3_kernel<<<(N + 255) / 256, 256>>>(N);
    scatter_kernel<<<(E + 255) / 256, 256>>>(row, col, vals, E);

    fused_kernel<<<(N + GEMM_ROWS - 1) / GEMM_ROWS, 128>>>(
        input, h0, W, lamda, alpha, l, out, N);
}

// round 4
// speedup vs baseline: 1.1447x; 1.1447x over previous
#include <cuda_runtime.h>
#include <math.h>

#define D 128
#define MAXN 50000
#define MAXE 800000
#define GEMM_ROWS 32

__device__ float g_support[MAXN * D];
__device__ int  g_cnt[MAXN];
__device__ int  g_offs[MAXN];     // after scatter: END offset per row
__device__ int  g_bsums[64];
__device__ int2 g_edge[MAXE];     // (col, val bits), binned by dest row

#define FMA2(acc, a, b) \
    asm("fma.rn.f32x2 %0, %1, %2, %0;" : "+l"(acc) : "l"(a), "l"(b))

__device__ __forceinline__ unsigned long long pack_dup(float f) {
    unsigned long long r;
    asm("mov.b64 %0, {%1, %1};" : "=l"(r) : "f"(f));
    return r;
}
__device__ __forceinline__ float lo_f(unsigned long long v) {
    return __uint_as_float((unsigned)(v & 0xffffffffull));
}
__device__ __forceinline__ float hi_f(unsigned long long v) {
    return __uint_as_float((unsigned)(v >> 32));
}

// ---------------- CSR build ----------------

__global__ void zero_cnt_kernel(int n) {
    int i = blockIdx.x * blockDim.x + threadIdx.x;
    if (i < n) g_cnt[i] = 0;
}

__global__ void hist_kernel(const int* __restrict__ row, int E) {
    int e = blockIdx.x * blockDim.x + threadIdx.x;
    if (e < E) atomicAdd(&g_cnt[row[e]], 1);
}

__global__ void scan1_kernel(int n) {
    __shared__ int s[1024];
    int i = blockIdx.x * 1024 + threadIdx.x;
    int v = (i < n) ? g_cnt[i] : 0;
    s[threadIdx.x] = v;
    __syncthreads();
    for (int d = 1; d < 1024; d <<= 1) {
        int t = (threadIdx.x >= d) ? s[threadIdx.x - d] : 0;
        __syncthreads();
        s[threadIdx.x] += t;
        __syncthreads();
    }
    if (i < n) g_offs[i] = s[threadIdx.x] - v;  // exclusive within block
    if (threadIdx.x == 1023) g_bsums[blockIdx.x] = s[1023];
}

__global__ void scan2_kernel(int nb) {
    __shared__ int s[64];
    int i = threadIdx.x;
    int v = (i < nb) ? g_bsums[i] : 0;
    s[i] = v;
    __syncthreads();
    for (int d = 1; d < 64; d <<= 1) {
        int t = (i >= d) ? s[i - d] : 0;
        __syncthreads();
        s[i] += t;
        __syncthreads();
    }
    if (i < nb) g_bsums[i] = s[i] - v;  // exclusive
}

__global__ void scan3_kernel(int n) {
    int i = blockIdx.x * blockDim.x + threadIdx.x;
    if (i < n) g_offs[i] += g_bsums[i >> 10];
}

__global__ void scatter_kernel(const int* __restrict__ row, const int* __restrict__ col,
                               const float* __restrict__ vals, int E) {
    int e = blockIdx.x * blockDim.x + threadIdx.x;
    if (e < E) {
        int pos = atomicAdd(&g_offs[row[e]], 1);  // offs becomes END after this kernel
        g_edge[pos] = make_int2(col[e], __float_as_int(vals[e]));
    }
}

// ---------------- gather SpMM: support = (1-alpha)*A*input + alpha*h0 ----------------
// One warp per destination row; edges processed in batches of 8 for MLP=8.

__global__ void gather_kernel(const float* __restrict__ input,
                              const float* __restrict__ h0,
                              const float* __restrict__ alpha_p, int N) {
    int wid  = (blockIdx.x * blockDim.x + threadIdx.x) >> 5;
    int lane = threadIdx.x & 31;
    if (wid >= N) return;
    int end = g_offs[wid];
    int beg = end - g_cnt[wid];
    const float4* in4 = (const float4*)input;

    float ax = 0.f, ay = 0.f, az = 0.f, aw = 0.f;
    int j = beg;
    for (; j + 8 <= end; j += 8) {
        int2 e[8];
#pragma unroll
        for (int q = 0; q < 8; q++) e[q] = __ldg(&g_edge[j + q]);
        float4 x[8];
#pragma unroll
        for (int q = 0; q < 8; q++) x[q] = __ldg(&in4[(size_t)e[q].x * 32 + lane]);
#pragma unroll
        for (int q = 0; q < 8; q++) {
            float v = __int_as_float(e[q].y);
            ax = fmaf(v, x[q].x, ax);
            ay = fmaf(v, x[q].y, ay);
            az = fmaf(v, x[q].z, az);
            aw = fmaf(v, x[q].w, aw);
        }
    }
    if (j + 4 <= end) {
        int2 e[4];
#pragma unroll
        for (int q = 0; q < 4; q++) e[q] = __ldg(&g_edge[j + q]);
        float4 x[4];
#pragma unroll
        for (int q = 0; q < 4; q++) x[q] = __ldg(&in4[(size_t)e[q].x * 32 + lane]);
#pragma unroll
        for (int q = 0; q < 4; q++) {
            float v = __int_as_float(e[q].y);
            ax = fmaf(v, x[q].x, ax);
            ay = fmaf(v, x[q].y, ay);
            az = fmaf(v, x[q].z, az);
            aw = fmaf(v, x[q].w, aw);
        }
        j += 4;
    }
    for (; j < end; j++) {
        int2 e = __ldg(&g_edge[j]);
        float v = __int_as_float(e.y);
        float4 x = __ldg(&in4[(size_t)e.x * 32 + lane]);
        ax = fmaf(v, x.x, ax);
        ay = fmaf(v, x.y, ay);
        az = fmaf(v, x.z, az);
        aw = fmaf(v, x.w, aw);
    }

    float a = *alpha_p, oma = 1.f - a;
    float4 h = ((const float4*)h0)[(size_t)wid * 32 + lane];
    float4 o = make_float4(fmaf(oma, ax, a * h.x),
                           fmaf(oma, ay, a * h.y),
                           fmaf(oma, az, a * h.z),
                           fmaf(oma, aw, a * h.w));
    ((float4*)g_support)[(size_t)wid * 32 + lane] = o;
}

// ---------------- GEMM: out = theta*(support@W) + (1-theta)*support ----------------
// Block = 128 threads (4 warps), 32 rows, 8 rows per warp; f32x2 packed FMA.

__global__ void __launch_bounds__(128) gemm_kernel(
        const float* __restrict__ W,
        const float* __restrict__ lamda_p,
        const int* __restrict__ l_p,
        float* __restrict__ out, int N) {
    __shared__ unsigned long long sp[GEMM_ROWS][D];  // 32 KB, sp[r][k] = (s,s)
    int tid  = threadIdx.x;
    int lane = tid & 31;
    int w    = tid >> 5;
    int rowBase = blockIdx.x * GEMM_ROWS;

    for (int t = tid; t < GEMM_ROWS * 32; t += 128) {
        int r = t >> 5;
        int q = t & 31;
        int gr = rowBase + r;
        float4 s4 = (gr < N) ? ((const float4*)g_support)[(size_t)gr * 32 + q]
                             : make_float4(0.f, 0.f, 0.f, 0.f);
        sp[r][q * 4 + 0] = pack_dup(s4.x);
        sp[r][q * 4 + 1] = pack_dup(s4.y);
        sp[r][q * 4 + 2] = pack_dup(s4.z);
        sp[r][q * 4 + 3] = pack_dup(s4.w);
    }
    __syncthreads();

    unsigned long long acc01[8], acc23[8];
#pragma unroll
    for (int r = 0; r < 8; r++) { acc01[r] = 0ull; acc23[r] = 0ull; }

    const ulonglong2* W2 = (const ulonglong2*)W;

#pragma unroll 4
    for (int kg = 0; kg < 32; kg++) {
        int k0 = kg * 4;
        ulonglong2 w0 = __ldg(&W2[(size_t)(k0 + 0) * 32 + lane]);
        ulonglong2 w1 = __ldg(&W2[(size_t)(k0 + 1) * 32 + lane]);
        ulonglong2 w2 = __ldg(&W2[(size_t)(k0 + 2) * 32 + lane]);
        ulonglong2 w3 = __ldg(&W2[(size_t)(k0 + 3) * 32 + lane]);
#pragma unroll
        for (int r = 0; r < 8; r++) {
            int rr = w * 8 + r;
            const ulonglong2* srow = (const ulonglong2*)sp[rr];
            ulonglong2 sA = srow[kg * 2 + 0];
            ulonglong2 sB = srow[kg * 2 + 1];
            FMA2(acc01[r], w0.x, sA.x); FMA2(acc23[r], w0.y, sA.x);
            FMA2(acc01[r], w1.x, sA.y); FMA2(acc23[r], w1.y, sA.y);
            FMA2(acc01[r], w2.x, sB.x); FMA2(acc23[r], w2.y, sB.x);
            FMA2(acc01[r], w3.x, sB.y); FMA2(acc23[r], w3.y, sB.y);
        }
    }

    float theta = logf(*lamda_p / (float)(*l_p) + 1.0f);
    float om = 1.0f - theta;

#pragma unroll
    for (int r = 0; r < 8; r++) {
        int rr = w * 8 + r;
        int gr = rowBase + rr;
        if (gr >= N) continue;
        const ulonglong2* srow = (const ulonglong2*)sp[rr];
        ulonglong2 s01 = srow[lane * 2 + 0];
        ulonglong2 s23 = srow[lane * 2 + 1];
        float4 o;
        o.x = fmaf(theta, lo_f(acc01[r]), om * lo_f(s01.x));
        o.y = fmaf(theta, hi_f(acc01[r]), om * lo_f(s01.y));
        o.z = fmaf(theta, lo_f(acc23[r]), om * lo_f(s23.x));
        o.w = fmaf(theta, hi_f(acc23[r]), om * lo_f(s23.y));
        ((float4*)out)[(size_t)gr * 32 + lane] = o;
    }
}

// ---------------- launch ----------------

extern "C" void kernel_launch(void* const* d_in, const int* in_sizes, int n_in,
                              void* d_out, int out_size) {
    const float* input  = (const float*)d_in[0];
    const float* h0     = (const float*)d_in[1];
    const float* vals   = (const float*)d_in[2];
    const float* W      = (const float*)d_in[3];
    const float* lamda  = (const float*)d_in[4];
    const float* alpha  = (const float*)d_in[5];
    const int*   row    = (const int*)d_in[6];
    const int*   col    = (const int*)d_in[7];
    const int*   l      = (const int*)d_in[8];
    float* out = (float*)d_out;

    int N = in_sizes[0] / D;
    int E = in_sizes[2];

    zero_cnt_kernel<<<(N + 255) / 256, 256>>>(N);
    hist_kernel<<<(E + 255) / 256, 256>>>(row, E);
    int nScanBlocks = (N + 1023) / 1024;
    scan1_kernel<<<nScanBlocks, 1024>>>(N);
    scan2_kernel<<<1, 64>>>(nScanBlocks);
    scan3_kernel<<<(N + 255) / 256, 256>>>(N);
    scatter_kernel<<<(E + 255) / 256, 256>>>(row, col, vals, E);

    gather_kernel<<<(N * 32 + 255) / 256, 256>>>(input, h0, alpha, N);

    gemm_kernel<<<(N + GEMM_ROWS - 1) / GEMM_ROWS, 128>>>(W, lamda, l, out, N);
}